// round 3
// baseline (speedup 1.0000x reference)
#include <cuda_runtime.h>
#include <cstdint>

#define N_NODES 50000
#define N_EDGES 400000
#define H 128
#define DEPTH 8
#define XS 18      // smem activation row stride (16 nodes + 2 pad)
#define WSS 132    // smem weight tile row stride (128 + 4 pad; keeps float4 alignment)

// ---------------- device scratch (no allocation allowed) ----------------
__device__ float g_agg[N_NODES * H];     // unnormalized attention-weighted sum
__device__ float g_denom[N_NODES];       // softmax denominator per dst
__device__ float g_p1[N_NODES];          // h . W_attn[:H]
__device__ float g_p2[N_NODES];          // h . W_attn[H:]
__device__ int   g_node_list[N_NODES];   // nodes bucketed by level
__device__ int   g_ebs[N_EDGES];         // bucketed edge src
__device__ int   g_ebd[N_EDGES];         // bucketed edge dst
__device__ int   g_cnts[32];             // [0:8) node cnt, [8:16) edge cnt, [16:24) node cursor, [24:32) edge cursor
__device__ int   g_node_off[DEPTH + 1];
__device__ int   g_edge_off[DEPTH + 1];

__device__ __forceinline__ int clamp_lvl(int l) {
    return l < 0 ? 0 : (l > 7 ? 7 : l);
}

__device__ __forceinline__ float sigmoidf_(float x) {
    return 1.0f / (1.0f + __expf(-x));
}

// ---------------- setup kernels ----------------

__global__ __launch_bounds__(256) void k_reset() {
    int idx = blockIdx.x * blockDim.x + threadIdx.x;
    int stride = gridDim.x * blockDim.x;
    float4* a4 = (float4*)g_agg;
    float4 z4 = make_float4(0.f, 0.f, 0.f, 0.f);
    for (int i = idx; i < N_NODES * H / 4; i += stride) a4[i] = z4;
    for (int i = idx; i < N_NODES; i += stride) g_denom[i] = 0.f;
    if (idx < 32) g_cnts[idx] = 0;
}

__global__ __launch_bounds__(256) void k_count(const int* __restrict__ fnl,
                                               const int* __restrict__ edst) {
    __shared__ int sc[16];
    int t = threadIdx.x;
    if (t < 16) sc[t] = 0;
    __syncthreads();
    int idx = blockIdx.x * blockDim.x + t;
    int stride = gridDim.x * blockDim.x;
    for (int i = idx; i < N_NODES + N_EDGES; i += stride) {
        if (i < N_NODES) {
            atomicAdd(&sc[clamp_lvl(__ldg(&fnl[i]))], 1);
        } else {
            int d = __ldg(&edst[i - N_NODES]);
            atomicAdd(&sc[8 + clamp_lvl(__ldg(&fnl[d]))], 1);
        }
    }
    __syncthreads();
    if (t < 16 && sc[t] > 0) atomicAdd(&g_cnts[t], sc[t]);
}

__global__ void k_scan() {
    if (threadIdx.x == 0 && blockIdx.x == 0) {
        int no = 0, eo = 0;
        for (int l = 0; l < 8; l++) {
            g_node_off[l] = no; no += g_cnts[l];
            g_edge_off[l] = eo; eo += g_cnts[8 + l];
        }
        g_node_off[8] = no;
        g_edge_off[8] = eo;
        for (int l = 0; l < 8; l++) {
            g_cnts[16 + l] = g_node_off[l];
            g_cnts[24 + l] = g_edge_off[l];
        }
    }
}

__global__ __launch_bounds__(256) void k_scatter(const int* __restrict__ fnl,
                                                 const int* __restrict__ esrc,
                                                 const int* __restrict__ edst) {
    __shared__ int scnt[16];
    __shared__ int sbase[16];
    int t = threadIdx.x;
    if (t < 16) scnt[t] = 0;
    __syncthreads();
    int i = blockIdx.x * blockDim.x + t;
    int key = -1, lp = 0;
    if (i < N_NODES) {
        key = clamp_lvl(__ldg(&fnl[i]));
        lp = atomicAdd(&scnt[key], 1);
    } else if (i < N_NODES + N_EDGES) {
        key = 8 + clamp_lvl(__ldg(&fnl[__ldg(&edst[i - N_NODES])]));
        lp = atomicAdd(&scnt[key], 1);
    }
    __syncthreads();
    if (t < 16 && scnt[t] > 0) sbase[t] = atomicAdd(&g_cnts[16 + t], scnt[t]);
    __syncthreads();
    if (key >= 0) {
        int pos = sbase[key] + lp;
        if (key < 8) {
            g_node_list[pos] = i;
        } else {
            int e = i - N_NODES;
            g_ebs[pos] = __ldg(&esrc[e]);
            g_ebd[pos] = __ldg(&edst[e]);
        }
    }
}

// copy node_embedding -> h, compute initial attention projections p1/p2
__global__ __launch_bounds__(256) void k_init(const float* __restrict__ ne,
                                              const float* __restrict__ wa,
                                              float* __restrict__ h) {
    int lane = threadIdx.x & 31;
    int w = (blockIdx.x * blockDim.x + threadIdx.x) >> 5;
    int nw = (gridDim.x * blockDim.x) >> 5;
    float4 a1 = *(const float4*)&wa[lane * 4];
    float4 a2 = *(const float4*)&wa[H + lane * 4];
    for (int n = w; n < N_NODES; n += nw) {
        float4 v = *(const float4*)&ne[(size_t)n * H + lane * 4];
        *(float4*)&h[(size_t)n * H + lane * 4] = v;
        float s1 = v.x * a1.x + v.y * a1.y + v.z * a1.z + v.w * a1.w;
        float s2 = v.x * a2.x + v.y * a2.y + v.z * a2.z + v.w * a2.w;
#pragma unroll
        for (int off = 16; off; off >>= 1) {
            s1 += __shfl_xor_sync(0xffffffffu, s1, off);
            s2 += __shfl_xor_sync(0xffffffffu, s2, off);
        }
        if (lane == 0) { g_p1[n] = s1; g_p2[n] = s2; }
    }
}

// ---------------- per-level edge pass ----------------
// One warp per edge: e = lrelu(p1[src]+p2[dst]+b); ex = exp(e);
// denom[dst] += ex;  agg[dst][:] += ex * h[src][:]
__global__ __launch_bounds__(256) void k_edge(const float* __restrict__ h,
                                              const float* __restrict__ b_attn,
                                              int level) {
    int start = g_edge_off[level], end = g_edge_off[level + 1];
    int lane = threadIdx.x & 31;
    int warp = (blockIdx.x * blockDim.x + threadIdx.x) >> 5;
    int nwarp = (gridDim.x * blockDim.x) >> 5;
    float b = __ldg(b_attn);
    for (int i = start + warp; i < end; i += nwarp) {
        int src = g_ebs[i], dst = g_ebd[i];
        float e = g_p1[src] + g_p2[dst] + b;
        e = e > 0.f ? e : 0.2f * e;                 // leaky_relu 0.2
        float ex = __expf(e);                       // no max-sub needed (|e| small)
        if (lane == 0) atomicAdd(&g_denom[dst], ex);
        float4 hv = __ldg((const float4*)(h + (size_t)src * H + lane * 4));
        float* dp = &g_agg[dst * H + lane * 4];
        asm volatile(
            "{ .reg .u64 p; cvta.to.global.u64 p, %0;\n\t"
            "red.global.add.v4.f32 [p], {%1, %2, %3, %4}; }"
            :: "l"(dp), "f"(hv.x * ex), "f"(hv.y * ex), "f"(hv.z * ex), "f"(hv.w * ex)
            : "memory");
    }
}

// ---------------- per-level GRU (tiled GEMMs over 16-node tiles) ----------------
// thread t: output features i0..i0+3 (i0=(t&31)*4), nodes nb..nb+1 (nb=(t>>5)*2)
__device__ __forceinline__ void gemm_tile(float (&acc)[4][2],
                                          const float* __restrict__ W, int ldw,
                                          int rowBase, int K,
                                          const float* xsm, float* ws,
                                          int i0, int nb, int t) {
    for (int kk = 0; kk < K; kk += 32) {
        int tw = K - kk; if (tw > 32) tw = 32;
        __syncthreads();                 // previous tile fully consumed
        if (tw == 32) {
#pragma unroll
            for (int p = 0; p < 16; p++) {
                int idx = t + p * 256;
                int o = idx >> 5, c = idx & 31;
                ws[c * WSS + o] = W[(rowBase + o) * ldw + kk + c];
            }
        } else {
            for (int idx = t; idx < 128 * tw; idx += 256) {
                int o = idx / tw, c = idx - o * tw;
                ws[c * WSS + o] = W[(rowBase + o) * ldw + kk + c];
            }
        }
        __syncthreads();
        if (tw == 32) {
#pragma unroll
            for (int c = 0; c < 32; c++) {
                float4 wv = *(const float4*)&ws[c * WSS + i0];
                float2 xv = *(const float2*)&xsm[(kk + c) * XS + nb];
                acc[0][0] += wv.x * xv.x; acc[0][1] += wv.x * xv.y;
                acc[1][0] += wv.y * xv.x; acc[1][1] += wv.y * xv.y;
                acc[2][0] += wv.z * xv.x; acc[2][1] += wv.z * xv.y;
                acc[3][0] += wv.w * xv.x; acc[3][1] += wv.w * xv.y;
            }
        } else {
            for (int c = 0; c < tw; c++) {
                float4 wv = *(const float4*)&ws[c * WSS + i0];
                float2 xv = *(const float2*)&xsm[(kk + c) * XS + nb];
                acc[0][0] += wv.x * xv.x; acc[0][1] += wv.x * xv.y;
                acc[1][0] += wv.y * xv.x; acc[1][1] += wv.y * xv.y;
                acc[2][0] += wv.z * xv.x; acc[2][1] += wv.z * xv.y;
                acc[3][0] += wv.w * xv.x; acc[3][1] += wv.w * xv.y;
            }
        }
    }
}

__global__ __launch_bounds__(256) void k_gru(
    float* __restrict__ h, const float* __restrict__ node_type,
    const float* __restrict__ Wmsg, const float* __restrict__ bmsg,
    const float* __restrict__ Wih, const float* __restrict__ Whh,
    const float* __restrict__ bih, const float* __restrict__ bhh,
    const float* __restrict__ Wattn, int level) {
    __shared__ __align__(16) float xs[131 * XS];   // agg (normalized) -> msg ; rows 128..130 = node_type
    __shared__ __align__(16) float hs[128 * XS];   // h (pre-update)
    __shared__ __align__(16) float ws[32 * WSS];   // weight tile
    __shared__ int   snode[16];
    __shared__ float sact[16];
    __shared__ float srd[16];

    int t = threadIdx.x;
    int start = g_node_off[level], end = g_node_off[level + 1];
    int cnt = end - start;
    int ntiles = (cnt + 15) >> 4;
    int i0 = (t & 31) * 4;
    int nb = (t >> 5) * 2;
    int lane = t & 31;

    for (int tile = blockIdx.x; tile < ntiles; tile += gridDim.x) {
        if (t < 16) {
            int slot = start + tile * 16 + t;
            int node = 0; float act = 0.f, rd = 0.f;
            if (slot < end) {
                node = g_node_list[slot];
                float d = g_denom[node];
                if (d > 0.f) { act = 1.f; rd = 1.f / (d + 1e-16f); }
            }
            snode[t] = node; sact[t] = act; srd[t] = rd;
        }
        __syncthreads();
        // stage normalized aggregate and h (transposed [feature][node])
        for (int idx = t; idx < 2048; idx += 256) {
            int n = idx >> 7, j = idx & 127;
            int node = snode[n];
            xs[j * XS + n] = g_agg[node * H + j] * srd[n];
            hs[j * XS + n] = h[(size_t)node * H + j];
        }
        for (int idx = t; idx < 48; idx += 256) {
            int n = idx / 3, c = idx - n * 3;
            xs[(128 + c) * XS + n] = node_type[snode[n] * 3 + c];
        }
        __syncthreads();

        // --- GEMM1: msg = a @ Wmsg^T + bmsg ---
        float acc[4][2];
#pragma unroll
        for (int di = 0; di < 4; di++) {
            float b = bmsg[i0 + di];
            acc[di][0] = b; acc[di][1] = b;
        }
        gemm_tile(acc, Wmsg, H, 0, H, xs, ws, i0, nb, t);
        __syncthreads();        // all reads of a done
#pragma unroll
        for (int di = 0; di < 4; di++) {
            xs[(i0 + di) * XS + nb + 0] = acc[di][0];
            xs[(i0 + di) * XS + nb + 1] = acc[di][1];
        }
        __syncthreads();

        // --- three gate chunks: r, z, n ---
        float rr[4][2], zz[4][2];
        for (int chunk = 0; chunk < 3; chunk++) {
            float ai[4][2], ah[4][2];
#pragma unroll
            for (int di = 0; di < 4; di++) {
                float b1 = bih[chunk * 128 + i0 + di];
                float b2 = bhh[chunk * 128 + i0 + di];
                ai[di][0] = b1; ai[di][1] = b1;
                ah[di][0] = b2; ah[di][1] = b2;
            }
            gemm_tile(ai, Wih, 131, chunk * 128, 131, xs, ws, i0, nb, t);
            gemm_tile(ah, Whh, 128, chunk * 128, 128, hs, ws, i0, nb, t);
            if (chunk == 0) {
#pragma unroll
                for (int di = 0; di < 4; di++) {
                    rr[di][0] = sigmoidf_(ai[di][0] + ah[di][0]);
                    rr[di][1] = sigmoidf_(ai[di][1] + ah[di][1]);
                }
            } else if (chunk == 1) {
#pragma unroll
                for (int di = 0; di < 4; di++) {
                    zz[di][0] = sigmoidf_(ai[di][0] + ah[di][0]);
                    zz[di][1] = sigmoidf_(ai[di][1] + ah[di][1]);
                }
            } else {
                float4 a1 = *(const float4*)&Wattn[i0];
                float4 a2 = *(const float4*)&Wattn[H + i0];
#pragma unroll
                for (int dn = 0; dn < 2; dn++) {
                    int node = snode[nb + dn];
                    bool act = sact[nb + dn] > 0.f;
                    float v0, v1, v2, v3;
                    {
                        float nn, hold;
                        nn = tanhf(ai[0][dn] + rr[0][dn] * ah[0][dn]);
                        hold = hs[(i0 + 0) * XS + nb + dn];
                        v0 = (1.f - zz[0][dn]) * nn + zz[0][dn] * hold;
                        nn = tanhf(ai[1][dn] + rr[1][dn] * ah[1][dn]);
                        hold = hs[(i0 + 1) * XS + nb + dn];
                        v1 = (1.f - zz[1][dn]) * nn + zz[1][dn] * hold;
                        nn = tanhf(ai[2][dn] + rr[2][dn] * ah[2][dn]);
                        hold = hs[(i0 + 2) * XS + nb + dn];
                        v2 = (1.f - zz[2][dn]) * nn + zz[2][dn] * hold;
                        nn = tanhf(ai[3][dn] + rr[3][dn] * ah[3][dn]);
                        hold = hs[(i0 + 3) * XS + nb + dn];
                        v3 = (1.f - zz[3][dn]) * nn + zz[3][dn] * hold;
                    }
                    if (act) {
                        *(float4*)(h + (size_t)node * H + i0) = make_float4(v0, v1, v2, v3);
                    }
                    // incremental attention-projection update (p1/p2) for updated nodes
                    float s1 = v0 * a1.x + v1 * a1.y + v2 * a1.z + v3 * a1.w;
                    float s2 = v0 * a2.x + v1 * a2.y + v2 * a2.z + v3 * a2.w;
#pragma unroll
                    for (int off = 16; off; off >>= 1) {
                        s1 += __shfl_xor_sync(0xffffffffu, s1, off);
                        s2 += __shfl_xor_sync(0xffffffffu, s2, off);
                    }
                    if (lane == 0 && act) { g_p1[node] = s1; g_p2[node] = s2; }
                }
            }
        }
        __syncthreads();   // protect smem before next tile
    }
}

// ---------------- launch ----------------
extern "C" void kernel_launch(void* const* d_in, const int* in_sizes, int n_in,
                              void* d_out, int out_size) {
    const float* node_embedding = (const float*)d_in[0];
    const float* node_type      = (const float*)d_in[1];
    const float* W_attn         = (const float*)d_in[2];
    const float* b_attn         = (const float*)d_in[3];
    const float* W_msg          = (const float*)d_in[4];
    const float* b_msg          = (const float*)d_in[5];
    const float* W_ih           = (const float*)d_in[6];
    const float* W_hh           = (const float*)d_in[7];
    const float* b_ih           = (const float*)d_in[8];
    const float* b_hh           = (const float*)d_in[9];
    const int*   edge_src       = (const int*)d_in[10];
    const int*   edge_dst       = (const int*)d_in[11];
    const int*   fnl            = (const int*)d_in[12];
    float* h = (float*)d_out;

    k_reset<<<4096, 256>>>();
    k_count<<<1758, 256>>>(fnl, edge_dst);
    k_scan<<<1, 32>>>();
    k_scatter<<<1758, 256>>>(fnl, edge_src, edge_dst);
    k_init<<<6250, 256>>>(node_embedding, W_attn, h);

    for (int k = 1; k < DEPTH; k++) {
        k_edge<<<2048, 256>>>(h, b_attn, k);
        k_gru<<<512, 256>>>(h, node_type, W_msg, b_msg, W_ih, W_hh, b_ih, b_hh,
                            W_attn, k);
    }
}

// round 4
// speedup vs baseline: 1.5058x; 1.5058x over previous
#include <cuda_runtime.h>
#include <cstdint>

#define N_NODES 50000
#define N_EDGES 400000
#define H 128
#define DEPTH 8
#define XS2 68      // smem activation row stride (64 nodes + 4 pad; mult of 4 for 16B loads)
#define WSS 132     // smem weight tile row stride (128 + 4 pad)

typedef unsigned long long ull;

// ---------------- device scratch (no allocation allowed) ----------------
__device__ float g_agg[N_NODES * H];
__device__ float g_denom[N_NODES];
__device__ float g_p1[N_NODES];
__device__ float g_p2[N_NODES];
__device__ int   g_node_list[N_NODES];
__device__ int   g_ebs[N_EDGES];
__device__ int   g_ebd[N_EDGES];
__device__ int   g_cnts[32];
__device__ int   g_node_off[DEPTH + 1];
__device__ int   g_edge_off[DEPTH + 1];
// k-major (transposed) weights, padded strides
__device__ float g_WihT[131 * 384];
__device__ float g_WhhT[128 * 384];
__device__ float g_WmsgT[128 * 128];

// smem float offsets for k_gru dynamic smem
#define SM_WS0  0
#define SM_WS1  4224
#define SM_XS   8448
#define SM_HS   17360            // 8448 + 8912 (131*68=8908 padded)
#define SM_META 26064            // 17360 + 8704 (128*68)
#define SM_FLOATS 26256
#define SM_BYTES (SM_FLOATS * 4)

__device__ __forceinline__ int clamp_lvl(int l) { return l < 0 ? 0 : (l > 7 ? 7 : l); }
__device__ __forceinline__ float sig_(float x) { return 1.0f / (1.0f + __expf(-x)); }
__device__ __forceinline__ float tanh_(float x) { return 2.0f / (1.0f + __expf(-2.0f * x)) - 1.0f; }

__device__ __forceinline__ ull pack2(float lo, float hi) {
    ull r; asm("mov.b64 %0,{%1,%2};" : "=l"(r) : "f"(lo), "f"(hi)); return r;
}
__device__ __forceinline__ void unpack2(ull v, float& lo, float& hi) {
    asm("mov.b64 {%0,%1},%2;" : "=f"(lo), "=f"(hi) : "l"(v));
}
__device__ __forceinline__ ull fma2(ull a, ull b, ull c) {
    ull d; asm("fma.rn.f32x2 %0,%1,%2,%3;" : "=l"(d) : "l"(a), "l"(b), "l"(c)); return d;
}
__device__ __forceinline__ ull add2(ull a, ull b) {
    ull d; asm("add.rn.f32x2 %0,%1,%2;" : "=l"(d) : "l"(a), "l"(b)); return d;
}
__device__ __forceinline__ ull sig2(ull v) {
    float a, b; unpack2(v, a, b); return pack2(sig_(a), sig_(b));
}

// ---------------- setup kernels ----------------

__global__ __launch_bounds__(256) void k_reset() {
    int idx = blockIdx.x * blockDim.x + threadIdx.x;
    int stride = gridDim.x * blockDim.x;
    float4* a4 = (float4*)g_agg;
    float4 z4 = make_float4(0.f, 0.f, 0.f, 0.f);
    for (int i = idx; i < N_NODES * H / 4; i += stride) a4[i] = z4;
    for (int i = idx; i < N_NODES; i += stride) g_denom[i] = 0.f;
    if (idx < 32) g_cnts[idx] = 0;
}

__global__ __launch_bounds__(256) void k_transpose(const float* __restrict__ Wih,
                                                   const float* __restrict__ Whh,
                                                   const float* __restrict__ Wmsg) {
    int i = blockIdx.x * blockDim.x + threadIdx.x;
    int stride = gridDim.x * blockDim.x;
    for (int idx = i; idx < 384 * 131; idx += stride) {
        int r = idx / 131, k = idx - r * 131;
        g_WihT[k * 384 + r] = Wih[idx];
    }
    for (int idx = i; idx < 384 * 128; idx += stride) {
        int r = idx >> 7, k = idx & 127;
        g_WhhT[k * 384 + r] = Whh[idx];
    }
    for (int idx = i; idx < 128 * 128; idx += stride) {
        int r = idx >> 7, k = idx & 127;
        g_WmsgT[k * 128 + r] = Wmsg[idx];
    }
}

__global__ __launch_bounds__(256) void k_count(const int* __restrict__ fnl,
                                               const int* __restrict__ edst) {
    __shared__ int sc[16];
    int t = threadIdx.x;
    if (t < 16) sc[t] = 0;
    __syncthreads();
    int idx = blockIdx.x * blockDim.x + t;
    int stride = gridDim.x * blockDim.x;
    for (int i = idx; i < N_NODES + N_EDGES; i += stride) {
        if (i < N_NODES) {
            atomicAdd(&sc[clamp_lvl(__ldg(&fnl[i]))], 1);
        } else {
            int d = __ldg(&edst[i - N_NODES]);
            atomicAdd(&sc[8 + clamp_lvl(__ldg(&fnl[d]))], 1);
        }
    }
    __syncthreads();
    if (t < 16 && sc[t] > 0) atomicAdd(&g_cnts[t], sc[t]);
}

__global__ void k_scan() {
    if (threadIdx.x == 0 && blockIdx.x == 0) {
        int no = 0, eo = 0;
        for (int l = 0; l < 8; l++) {
            g_node_off[l] = no; no += g_cnts[l];
            g_edge_off[l] = eo; eo += g_cnts[8 + l];
        }
        g_node_off[8] = no;
        g_edge_off[8] = eo;
        for (int l = 0; l < 8; l++) {
            g_cnts[16 + l] = g_node_off[l];
            g_cnts[24 + l] = g_edge_off[l];
        }
    }
}

__global__ __launch_bounds__(256) void k_scatter(const int* __restrict__ fnl,
                                                 const int* __restrict__ esrc,
                                                 const int* __restrict__ edst) {
    __shared__ int scnt[16];
    __shared__ int sbase[16];
    int t = threadIdx.x;
    if (t < 16) scnt[t] = 0;
    __syncthreads();
    int i = blockIdx.x * blockDim.x + t;
    int key = -1, lp = 0;
    if (i < N_NODES) {
        key = clamp_lvl(__ldg(&fnl[i]));
        lp = atomicAdd(&scnt[key], 1);
    } else if (i < N_NODES + N_EDGES) {
        key = 8 + clamp_lvl(__ldg(&fnl[__ldg(&edst[i - N_NODES])]));
        lp = atomicAdd(&scnt[key], 1);
    }
    __syncthreads();
    if (t < 16 && scnt[t] > 0) sbase[t] = atomicAdd(&g_cnts[16 + t], scnt[t]);
    __syncthreads();
    if (key >= 0) {
        int pos = sbase[key] + lp;
        if (key < 8) {
            g_node_list[pos] = i;
        } else {
            int e = i - N_NODES;
            g_ebs[pos] = __ldg(&esrc[e]);
            g_ebd[pos] = __ldg(&edst[e]);
        }
    }
}

__global__ __launch_bounds__(256) void k_init(const float* __restrict__ ne,
                                              const float* __restrict__ wa,
                                              float* __restrict__ h) {
    int lane = threadIdx.x & 31;
    int w = (blockIdx.x * blockDim.x + threadIdx.x) >> 5;
    int nw = (gridDim.x * blockDim.x) >> 5;
    float4 a1 = *(const float4*)&wa[lane * 4];
    float4 a2 = *(const float4*)&wa[H + lane * 4];
    for (int n = w; n < N_NODES; n += nw) {
        float4 v = *(const float4*)&ne[(size_t)n * H + lane * 4];
        *(float4*)&h[(size_t)n * H + lane * 4] = v;
        float s1 = v.x * a1.x + v.y * a1.y + v.z * a1.z + v.w * a1.w;
        float s2 = v.x * a2.x + v.y * a2.y + v.z * a2.z + v.w * a2.w;
#pragma unroll
        for (int off = 16; off; off >>= 1) {
            s1 += __shfl_xor_sync(0xffffffffu, s1, off);
            s2 += __shfl_xor_sync(0xffffffffu, s2, off);
        }
        if (lane == 0) { g_p1[n] = s1; g_p2[n] = s2; }
    }
}

// ---------------- per-level edge pass ----------------
__global__ __launch_bounds__(256) void k_edge(const float* __restrict__ h,
                                              const float* __restrict__ b_attn,
                                              int level) {
    int start = g_edge_off[level], end = g_edge_off[level + 1];
    int lane = threadIdx.x & 31;
    int warp = (blockIdx.x * blockDim.x + threadIdx.x) >> 5;
    int nwarp = (gridDim.x * blockDim.x) >> 5;
    float b = __ldg(b_attn);
    for (int i = start + warp; i < end; i += nwarp) {
        int src = g_ebs[i], dst = g_ebd[i];
        float e = g_p1[src] + g_p2[dst] + b;
        e = e > 0.f ? e : 0.2f * e;
        float ex = __expf(e);
        if (lane == 0) atomicAdd(&g_denom[dst], ex);
        float4 hv = __ldg((const float4*)(h + (size_t)src * H + lane * 4));
        float* dp = &g_agg[dst * H + lane * 4];
        asm volatile(
            "{ .reg .u64 p; cvta.to.global.u64 p, %0;\n\t"
            "red.global.add.v4.f32 [p], {%1, %2, %3, %4}; }"
            :: "l"(dp), "f"(hv.x * ex), "f"(hv.y * ex), "f"(hv.z * ex), "f"(hv.w * ex)
            : "memory");
    }
}

// ---------------- GEMM over a 64-node tile, f32x2 packed, cp.async dbl-buffered --
// thread: features i0..i0+3 (i0 = lane*4), nodes nb0..nb0+7 (nb0 = warp*8)
// acc[di][p] = packed pair (node nb0+2p, nb0+2p+1) for feature i0+di
__device__ __forceinline__ void issue_tile(const float* __restrict__ WT, int ldT,
                                           int rowBase, int kk, int tw,
                                           float* wsbuf, int t) {
    int nops = tw * 32;
    for (int idx = t; idx < nops; idx += 256) {
        int c = idx >> 5, seg = (idx & 31) << 2;
        unsigned dst = (unsigned)__cvta_generic_to_shared(wsbuf + c * WSS + seg);
        const float* src = WT + (size_t)(kk + c) * ldT + rowBase + seg;
        asm volatile("cp.async.cg.shared.global [%0],[%1],16;"
                     :: "r"(dst), "l"(src) : "memory");
    }
}

__device__ __forceinline__ void gemm64(ull (&acc)[4][4], const float* __restrict__ WT,
                                       int ldT, int rowBase, int K,
                                       const float* xsm, float* ws0, float* ws1,
                                       int i0, int nb0, int t) {
    int nkt = (K + 31) >> 5;
    issue_tile(WT, ldT, rowBase, 0, K < 32 ? K : 32, ws0, t);
    asm volatile("cp.async.commit_group;" ::: "memory");
    for (int kt = 0; kt < nkt; kt++) {
        int kk = kt << 5;
        int tw = K - kk; if (tw > 32) tw = 32;
        float* cur = (kt & 1) ? ws1 : ws0;
        if (kt + 1 < nkt) {
            float* nxt = (kt & 1) ? ws0 : ws1;
            int kk2 = kk + 32;
            int tw2 = K - kk2; if (tw2 > 32) tw2 = 32;
            issue_tile(WT, ldT, rowBase, kk2, tw2, nxt, t);
            asm volatile("cp.async.commit_group;" ::: "memory");
            asm volatile("cp.async.wait_group 1;" ::: "memory");
        } else {
            asm volatile("cp.async.wait_group 0;" ::: "memory");
        }
        __syncthreads();
        const float* xrow = xsm + kk * XS2 + nb0;
        if (tw == 32) {
#pragma unroll 4
            for (int c = 0; c < 32; c++) {
                float4 wv = *(const float4*)&cur[c * WSS + i0];
                ulonglong2 xa = *(const ulonglong2*)(xrow + c * XS2);
                ulonglong2 xb = *(const ulonglong2*)(xrow + c * XS2 + 4);
                ull w0 = pack2(wv.x, wv.x), w1 = pack2(wv.y, wv.y);
                ull w2 = pack2(wv.z, wv.z), w3 = pack2(wv.w, wv.w);
                acc[0][0] = fma2(w0, xa.x, acc[0][0]); acc[0][1] = fma2(w0, xa.y, acc[0][1]);
                acc[0][2] = fma2(w0, xb.x, acc[0][2]); acc[0][3] = fma2(w0, xb.y, acc[0][3]);
                acc[1][0] = fma2(w1, xa.x, acc[1][0]); acc[1][1] = fma2(w1, xa.y, acc[1][1]);
                acc[1][2] = fma2(w1, xb.x, acc[1][2]); acc[1][3] = fma2(w1, xb.y, acc[1][3]);
                acc[2][0] = fma2(w2, xa.x, acc[2][0]); acc[2][1] = fma2(w2, xa.y, acc[2][1]);
                acc[2][2] = fma2(w2, xb.x, acc[2][2]); acc[2][3] = fma2(w2, xb.y, acc[2][3]);
                acc[3][0] = fma2(w3, xa.x, acc[3][0]); acc[3][1] = fma2(w3, xa.y, acc[3][1]);
                acc[3][2] = fma2(w3, xb.x, acc[3][2]); acc[3][3] = fma2(w3, xb.y, acc[3][3]);
            }
        } else {
            for (int c = 0; c < tw; c++) {
                float4 wv = *(const float4*)&cur[c * WSS + i0];
                ulonglong2 xa = *(const ulonglong2*)(xrow + c * XS2);
                ulonglong2 xb = *(const ulonglong2*)(xrow + c * XS2 + 4);
                ull w0 = pack2(wv.x, wv.x), w1 = pack2(wv.y, wv.y);
                ull w2 = pack2(wv.z, wv.z), w3 = pack2(wv.w, wv.w);
                acc[0][0] = fma2(w0, xa.x, acc[0][0]); acc[0][1] = fma2(w0, xa.y, acc[0][1]);
                acc[0][2] = fma2(w0, xb.x, acc[0][2]); acc[0][3] = fma2(w0, xb.y, acc[0][3]);
                acc[1][0] = fma2(w1, xa.x, acc[1][0]); acc[1][1] = fma2(w1, xa.y, acc[1][1]);
                acc[1][2] = fma2(w1, xb.x, acc[1][2]); acc[1][3] = fma2(w1, xb.y, acc[1][3]);
                acc[2][0] = fma2(w2, xa.x, acc[2][0]); acc[2][1] = fma2(w2, xa.y, acc[2][1]);
                acc[2][2] = fma2(w2, xb.x, acc[2][2]); acc[2][3] = fma2(w2, xb.y, acc[2][3]);
                acc[3][0] = fma2(w3, xa.x, acc[3][0]); acc[3][1] = fma2(w3, xa.y, acc[3][1]);
                acc[3][2] = fma2(w3, xb.x, acc[3][2]); acc[3][3] = fma2(w3, xb.y, acc[3][3]);
            }
        }
        __syncthreads();
    }
}

__global__ __launch_bounds__(256, 1) void k_gru(
    float* __restrict__ h, const float* __restrict__ node_type,
    const float* __restrict__ bmsg,
    const float* __restrict__ bih, const float* __restrict__ bhh,
    const float* __restrict__ Wattn, int level) {
    extern __shared__ __align__(16) float sm[];
    float* ws0 = sm + SM_WS0;
    float* ws1 = sm + SM_WS1;
    float* xs  = sm + SM_XS;
    float* hs  = sm + SM_HS;
    int*   snode = (int*)(sm + SM_META);
    float* sact  = sm + SM_META + 64;
    float* srd   = sm + SM_META + 128;

    int t = threadIdx.x;
    int start = g_node_off[level], end = g_node_off[level + 1];
    int cnt = end - start;
    int ntiles = (cnt + 63) >> 6;
    int lane = t & 31;
    int i0 = lane << 2;
    int warp = t >> 5;
    int nb0 = warp << 3;

    for (int tile = blockIdx.x; tile < ntiles; tile += gridDim.x) {
        if (t < 64) {
            int slot = start + (tile << 6) + t;
            int node = 0; float act = 0.f, rd = 0.f;
            if (slot < end) {
                node = g_node_list[slot];
                float d = g_denom[node];
                if (d > 0.f) { act = 1.f; rd = 1.f / (d + 1e-16f); }
            }
            snode[t] = node; sact[t] = act; srd[t] = rd;
        }
        __syncthreads();
        // stage agg*rd and h, feature-major [feat][node]
        for (int idx = t; idx < 2048; idx += 256) {
            int n = idx & 63, j4 = idx >> 6;
            int node = snode[n];
            float rd = srd[n];
            float4 av = *(const float4*)&g_agg[(size_t)node * H + (j4 << 2)];
            float4 hv = *(const float4*)&h[(size_t)node * H + (j4 << 2)];
            int jb = j4 << 2;
            xs[(jb + 0) * XS2 + n] = av.x * rd;
            xs[(jb + 1) * XS2 + n] = av.y * rd;
            xs[(jb + 2) * XS2 + n] = av.z * rd;
            xs[(jb + 3) * XS2 + n] = av.w * rd;
            hs[(jb + 0) * XS2 + n] = hv.x;
            hs[(jb + 1) * XS2 + n] = hv.y;
            hs[(jb + 2) * XS2 + n] = hv.z;
            hs[(jb + 3) * XS2 + n] = hv.w;
        }
        for (int idx = t; idx < 192; idx += 256) {
            int n = idx & 63, c = idx >> 6;
            xs[(128 + c) * XS2 + n] = node_type[(size_t)snode[n] * 3 + c];
        }
        __syncthreads();

        // --- GEMM1: msg = xs(agg) @ WmsgT + bmsg; write back into xs rows 0..127
        {
            ull acc[4][4];
#pragma unroll
            for (int di = 0; di < 4; di++) {
                float b = bmsg[i0 + di];
                ull bp = pack2(b, b);
                acc[di][0] = bp; acc[di][1] = bp; acc[di][2] = bp; acc[di][3] = bp;
            }
            gemm64(acc, g_WmsgT, 128, 0, 128, xs, ws0, ws1, i0, nb0, t);
#pragma unroll
            for (int di = 0; di < 4; di++)
#pragma unroll
                for (int p = 0; p < 4; p++)
                    *(ull*)&xs[(i0 + di) * XS2 + nb0 + (p << 1)] = acc[di][p];
        }
        __syncthreads();

        // --- gates: chunk 0 = r, 1 = z, 2 = n + epilogue ---
        ull rr[4][4], zz[4][4];
        for (int chunk = 0; chunk < 3; chunk++) {
            ull ai[4][4], ah[4][4];
#pragma unroll
            for (int di = 0; di < 4; di++) {
                float b1 = bih[chunk * H + i0 + di];
                float b2 = bhh[chunk * H + i0 + di];
                ull p1v = pack2(b1, b1), p2v = pack2(b2, b2);
#pragma unroll
                for (int p = 0; p < 4; p++) { ai[di][p] = p1v; ah[di][p] = p2v; }
            }
            gemm64(ai, g_WihT, 384, chunk * H, 131, xs, ws0, ws1, i0, nb0, t);
            gemm64(ah, g_WhhT, 384, chunk * H, 128, hs, ws0, ws1, i0, nb0, t);
            if (chunk == 0) {
#pragma unroll
                for (int di = 0; di < 4; di++)
#pragma unroll
                    for (int p = 0; p < 4; p++)
                        rr[di][p] = sig2(add2(ai[di][p], ah[di][p]));
            } else if (chunk == 1) {
#pragma unroll
                for (int di = 0; di < 4; di++)
#pragma unroll
                    for (int p = 0; p < 4; p++)
                        zz[di][p] = sig2(add2(ai[di][p], ah[di][p]));
            } else {
                float4 a1 = *(const float4*)&Wattn[i0];
                float4 a2 = *(const float4*)&Wattn[H + i0];
#pragma unroll
                for (int p = 0; p < 4; p++) {
                    float v[2][4];
#pragma unroll
                    for (int di = 0; di < 4; di++) {
                        float in0, in1, hn0, hn1, r0, r1, z0, z1, h0, h1;
                        unpack2(ai[di][p], in0, in1);
                        unpack2(ah[di][p], hn0, hn1);
                        unpack2(rr[di][p], r0, r1);
                        unpack2(zz[di][p], z0, z1);
                        ull hold = *(const ull*)&hs[(i0 + di) * XS2 + nb0 + (p << 1)];
                        unpack2(hold, h0, h1);
                        float n0 = tanh_(in0 + r0 * hn0);
                        float n1 = tanh_(in1 + r1 * hn1);
                        v[0][di] = (1.f - z0) * n0 + z0 * h0;
                        v[1][di] = (1.f - z1) * n1 + z1 * h1;
                    }
#pragma unroll
                    for (int half = 0; half < 2; half++) {
                        int nn = nb0 + (p << 1) + half;
                        int node = snode[nn];
                        bool act = sact[nn] > 0.f;
                        if (act) {
                            *(float4*)&h[(size_t)node * H + i0] =
                                make_float4(v[half][0], v[half][1], v[half][2], v[half][3]);
                        }
                        float s1 = v[half][0] * a1.x + v[half][1] * a1.y +
                                   v[half][2] * a1.z + v[half][3] * a1.w;
                        float s2 = v[half][0] * a2.x + v[half][1] * a2.y +
                                   v[half][2] * a2.z + v[half][3] * a2.w;
#pragma unroll
                        for (int off = 16; off; off >>= 1) {
                            s1 += __shfl_xor_sync(0xffffffffu, s1, off);
                            s2 += __shfl_xor_sync(0xffffffffu, s2, off);
                        }
                        if (lane == 0 && act) { g_p1[node] = s1; g_p2[node] = s2; }
                    }
                }
            }
        }
        __syncthreads();   // protect smem before next tile
    }
}

// ---------------- launch ----------------
extern "C" void kernel_launch(void* const* d_in, const int* in_sizes, int n_in,
                              void* d_out, int out_size) {
    const float* node_embedding = (const float*)d_in[0];
    const float* node_type      = (const float*)d_in[1];
    const float* W_attn         = (const float*)d_in[2];
    const float* b_attn         = (const float*)d_in[3];
    const float* W_msg          = (const float*)d_in[4];
    const float* b_msg          = (const float*)d_in[5];
    const float* W_ih           = (const float*)d_in[6];
    const float* W_hh           = (const float*)d_in[7];
    const float* b_ih           = (const float*)d_in[8];
    const float* b_hh           = (const float*)d_in[9];
    const int*   edge_src       = (const int*)d_in[10];
    const int*   edge_dst       = (const int*)d_in[11];
    const int*   fnl            = (const int*)d_in[12];
    float* h = (float*)d_out;

    cudaFuncSetAttribute(k_gru, cudaFuncAttributeMaxDynamicSharedMemorySize, SM_BYTES);

    k_reset<<<4096, 256>>>();
    k_transpose<<<197, 256>>>(W_ih, W_hh, W_msg);
    k_count<<<1758, 256>>>(fnl, edge_dst);
    k_scan<<<1, 32>>>();
    k_scatter<<<1758, 256>>>(fnl, edge_src, edge_dst);
    k_init<<<6250, 256>>>(node_embedding, W_attn, h);

    for (int k = 1; k < DEPTH; k++) {
        k_edge<<<2048, 256>>>(h, b_attn, k);
        k_gru<<<148, 256, SM_BYTES>>>(h, node_type, b_msg, b_ih, b_hh, W_attn, k);
    }
}

// round 5
// speedup vs baseline: 1.8180x; 1.2073x over previous
#include <cuda_runtime.h>
#include <cstdint>

#define N_NODES 50000
#define N_EDGES 400000
#define H 128
#define DEPTH 8
#define TILE_N 48      // nodes per block tile
#define XS3 52         // smem activation row stride (48 + 4 pad)
#define WSS 132        // smem weight tile row stride (128 + 4 pad)

typedef unsigned long long ull;

// ---------------- device scratch (no allocation allowed) ----------------
__device__ float g_agg[N_NODES * H];
__device__ float g_denom[N_NODES];
__device__ float g_p1[N_NODES];
__device__ float g_p2[N_NODES];
__device__ int   g_node_list[N_NODES];
__device__ int   g_ebs[N_EDGES];
__device__ int   g_ebd[N_EDGES];
__device__ int   g_cnts[32];
__device__ int   g_node_off[DEPTH + 1];
__device__ int   g_edge_off[DEPTH + 1];
// fused + transposed weights (k-major, [128 k][384 rows])
__device__ float g_WbigT[128 * 384];   // (W_ih[:,:128] @ W_msg) transposed
__device__ float g_WhhT[128 * 384];
__device__ float g_bbig[384];          // b_ih + W_ih[:,:128] @ b_msg

// smem float offsets for k_gru dynamic smem
#define SM_WS0   0
#define SM_WS1   4224
#define SM_XS    8448               // 128 x 52 = 6656
#define SM_HS    15104              // 128 x 52 = 6656
#define SM_NT    21760              // 3 x 384 = 1152 (W_ih node-type columns)
#define SM_META  22912              // snode/sact/srd/stype: 4 x 48
#define SM_FLOATS 23104
#define SM_BYTES (SM_FLOATS * 4)

__device__ __forceinline__ int clamp_lvl(int l) { return l < 0 ? 0 : (l > 7 ? 7 : l); }
__device__ __forceinline__ float sig_(float x) { return 1.0f / (1.0f + __expf(-x)); }
__device__ __forceinline__ float tanh_(float x) { return 2.0f / (1.0f + __expf(-2.0f * x)) - 1.0f; }

__device__ __forceinline__ ull pack2(float lo, float hi) {
    ull r; asm("mov.b64 %0,{%1,%2};" : "=l"(r) : "f"(lo), "f"(hi)); return r;
}
__device__ __forceinline__ void unpack2(ull v, float& lo, float& hi) {
    asm("mov.b64 {%0,%1},%2;" : "=f"(lo), "=f"(hi) : "l"(v));
}
__device__ __forceinline__ ull fma2(ull a, ull b, ull c) {
    ull d; asm("fma.rn.f32x2 %0,%1,%2,%3;" : "=l"(d) : "l"(a), "l"(b), "l"(c)); return d;
}
__device__ __forceinline__ ull add2(ull a, ull b) {
    ull d; asm("add.rn.f32x2 %0,%1,%2;" : "=l"(d) : "l"(a), "l"(b)); return d;
}
__device__ __forceinline__ ull sig2(ull v) {
    float a, b; unpack2(v, a, b); return pack2(sig_(a), sig_(b));
}

// ---------------- setup kernels ----------------

__global__ __launch_bounds__(256) void k_reset() {
    int idx = blockIdx.x * blockDim.x + threadIdx.x;
    int stride = gridDim.x * blockDim.x;
    float4* a4 = (float4*)g_agg;
    float4 z4 = make_float4(0.f, 0.f, 0.f, 0.f);
    for (int i = idx; i < N_NODES * H / 4; i += stride) a4[i] = z4;
    for (int i = idx; i < N_NODES; i += stride) g_denom[i] = 0.f;
    if (idx < 32) g_cnts[idx] = 0;
}

// W_big[r,m] = sum_j W_ih[r,j] * W_msg[j,m]; b_big[r] = b_ih[r] + sum_j W_ih[r,j]*b_msg[j]
__global__ __launch_bounds__(128) void k_fuse(const float* __restrict__ Wih,
                                              const float* __restrict__ Wmsg,
                                              const float* __restrict__ bih,
                                              const float* __restrict__ bmsg) {
    int r = blockIdx.x;        // 0..383
    int m = threadIdx.x;       // 0..127
    __shared__ float wr[128];
    wr[m] = Wih[r * 131 + m];
    __syncthreads();
    float s = 0.f;
#pragma unroll 8
    for (int j = 0; j < 128; j++) s += wr[j] * Wmsg[j * 128 + m];
    g_WbigT[m * 384 + r] = s;
    if (m == 0) {
        float b = bih[r];
        for (int j = 0; j < 128; j++) b += wr[j] * bmsg[j];
        g_bbig[r] = b;
    }
}

__global__ __launch_bounds__(256) void k_transpose(const float* __restrict__ Whh) {
    int i = blockIdx.x * blockDim.x + threadIdx.x;
    int stride = gridDim.x * blockDim.x;
    for (int idx = i; idx < 384 * 128; idx += stride) {
        int r = idx >> 7, k = idx & 127;
        g_WhhT[k * 384 + r] = Whh[idx];
    }
}

__global__ __launch_bounds__(256) void k_count(const int* __restrict__ fnl,
                                               const int* __restrict__ edst) {
    __shared__ int sc[16];
    int t = threadIdx.x;
    if (t < 16) sc[t] = 0;
    __syncthreads();
    int idx = blockIdx.x * blockDim.x + t;
    int stride = gridDim.x * blockDim.x;
    for (int i = idx; i < N_NODES + N_EDGES; i += stride) {
        if (i < N_NODES) {
            atomicAdd(&sc[clamp_lvl(__ldg(&fnl[i]))], 1);
        } else {
            int d = __ldg(&edst[i - N_NODES]);
            atomicAdd(&sc[8 + clamp_lvl(__ldg(&fnl[d]))], 1);
        }
    }
    __syncthreads();
    if (t < 16 && sc[t] > 0) atomicAdd(&g_cnts[t], sc[t]);
}

__global__ void k_scan() {
    if (threadIdx.x == 0 && blockIdx.x == 0) {
        int no = 0, eo = 0;
        for (int l = 0; l < 8; l++) {
            g_node_off[l] = no; no += g_cnts[l];
            g_edge_off[l] = eo; eo += g_cnts[8 + l];
        }
        g_node_off[8] = no;
        g_edge_off[8] = eo;
        for (int l = 0; l < 8; l++) {
            g_cnts[16 + l] = g_node_off[l];
            g_cnts[24 + l] = g_edge_off[l];
        }
    }
}

__global__ __launch_bounds__(256) void k_scatter(const int* __restrict__ fnl,
                                                 const int* __restrict__ esrc,
                                                 const int* __restrict__ edst) {
    __shared__ int scnt[16];
    __shared__ int sbase[16];
    int t = threadIdx.x;
    if (t < 16) scnt[t] = 0;
    __syncthreads();
    int i = blockIdx.x * blockDim.x + t;
    int key = -1, lp = 0;
    if (i < N_NODES) {
        key = clamp_lvl(__ldg(&fnl[i]));
        lp = atomicAdd(&scnt[key], 1);
    } else if (i < N_NODES + N_EDGES) {
        key = 8 + clamp_lvl(__ldg(&fnl[__ldg(&edst[i - N_NODES])]));
        lp = atomicAdd(&scnt[key], 1);
    }
    __syncthreads();
    if (t < 16 && scnt[t] > 0) sbase[t] = atomicAdd(&g_cnts[16 + t], scnt[t]);
    __syncthreads();
    if (key >= 0) {
        int pos = sbase[key] + lp;
        if (key < 8) {
            g_node_list[pos] = i;
        } else {
            int e = i - N_NODES;
            g_ebs[pos] = __ldg(&esrc[e]);
            g_ebd[pos] = __ldg(&edst[e]);
        }
    }
}

__global__ __launch_bounds__(256) void k_init(const float* __restrict__ ne,
                                              const float* __restrict__ wa,
                                              float* __restrict__ h) {
    int lane = threadIdx.x & 31;
    int w = (blockIdx.x * blockDim.x + threadIdx.x) >> 5;
    int nw = (gridDim.x * blockDim.x) >> 5;
    float4 a1 = *(const float4*)&wa[lane * 4];
    float4 a2 = *(const float4*)&wa[H + lane * 4];
    for (int n = w; n < N_NODES; n += nw) {
        float4 v = *(const float4*)&ne[(size_t)n * H + lane * 4];
        *(float4*)&h[(size_t)n * H + lane * 4] = v;
        float s1 = v.x * a1.x + v.y * a1.y + v.z * a1.z + v.w * a1.w;
        float s2 = v.x * a2.x + v.y * a2.y + v.z * a2.z + v.w * a2.w;
#pragma unroll
        for (int off = 16; off; off >>= 1) {
            s1 += __shfl_xor_sync(0xffffffffu, s1, off);
            s2 += __shfl_xor_sync(0xffffffffu, s2, off);
        }
        if (lane == 0) { g_p1[n] = s1; g_p2[n] = s2; }
    }
}

// ---------------- per-level edge pass ----------------
__global__ __launch_bounds__(256) void k_edge(const float* __restrict__ h,
                                              const float* __restrict__ b_attn,
                                              int level) {
    int start = g_edge_off[level], end = g_edge_off[level + 1];
    int lane = threadIdx.x & 31;
    int warp = (blockIdx.x * blockDim.x + threadIdx.x) >> 5;
    int nwarp = (gridDim.x * blockDim.x) >> 5;
    float b = __ldg(b_attn);
    for (int i = start + warp; i < end; i += nwarp) {
        int src = g_ebs[i], dst = g_ebd[i];
        float e = g_p1[src] + g_p2[dst] + b;
        e = e > 0.f ? e : 0.2f * e;
        float ex = __expf(e);
        if (lane == 0) atomicAdd(&g_denom[dst], ex);
        float4 hv = __ldg((const float4*)(h + (size_t)src * H + lane * 4));
        float* dp = &g_agg[dst * H + lane * 4];
        asm volatile(
            "{ .reg .u64 p; cvta.to.global.u64 p, %0;\n\t"
            "red.global.add.v4.f32 [p], {%1, %2, %3, %4}; }"
            :: "l"(dp), "f"(hv.x * ex), "f"(hv.y * ex), "f"(hv.z * ex), "f"(hv.w * ex)
            : "memory");
    }
}

// ---------------- GEMM over a 48-node tile ----------------
// thread: features i0..i0+3 (i0 = lane*4), nodes nb0..nb0+5 (nb0 = warp*6), 3 f32x2 pairs
__device__ __forceinline__ void issue_tile(const float* __restrict__ WT, int rowBase,
                                           int kk, float* wsbuf, int t) {
#pragma unroll
    for (int p = 0; p < 4; p++) {
        int idx = t + p * 256;               // 0..1023
        int c = idx >> 5, seg = (idx & 31) << 2;
        unsigned dst = (unsigned)__cvta_generic_to_shared(wsbuf + c * WSS + seg);
        const float* src = WT + (size_t)(kk + c) * 384 + rowBase + seg;
        asm volatile("cp.async.cg.shared.global [%0],[%1],16;"
                     :: "r"(dst), "l"(src) : "memory");
    }
}

// K fixed = 128 (4 tiles of 32), weight stride fixed = 384.
__device__ __forceinline__ void gemm48(ull (&acc)[4][3], const float* __restrict__ WT,
                                       int rowBase, const float* xsm,
                                       float* ws0, float* ws1, int i0, int nb0, int t) {
    __syncthreads();                       // prior consumers of ws0/xsm done
    issue_tile(WT, rowBase, 0, ws0, t);
    asm volatile("cp.async.commit_group;" ::: "memory");
#pragma unroll
    for (int kt = 0; kt < 4; kt++) {
        asm volatile("cp.async.wait_group 0;" ::: "memory");
        __syncthreads();                   // everyone's copies landed, prev tile consumed
        if (kt < 3) {
            issue_tile(WT, rowBase, (kt + 1) << 5, (kt & 1) ? ws0 : ws1, t);
            asm volatile("cp.async.commit_group;" ::: "memory");
        }
        const float* cur = (kt & 1) ? ws1 : ws0;
        const float* xrow = xsm + ((kt << 5)) * XS3 + nb0;
#pragma unroll 4
        for (int c = 0; c < 32; c++) {
            float4 wv = *(const float4*)&cur[c * WSS + i0];
            ull x0 = *(const ull*)(xrow + c * XS3);
            ull x1 = *(const ull*)(xrow + c * XS3 + 2);
            ull x2 = *(const ull*)(xrow + c * XS3 + 4);
            ull w0 = pack2(wv.x, wv.x), w1 = pack2(wv.y, wv.y);
            ull w2 = pack2(wv.z, wv.z), w3 = pack2(wv.w, wv.w);
            acc[0][0] = fma2(w0, x0, acc[0][0]);
            acc[0][1] = fma2(w0, x1, acc[0][1]);
            acc[0][2] = fma2(w0, x2, acc[0][2]);
            acc[1][0] = fma2(w1, x0, acc[1][0]);
            acc[1][1] = fma2(w1, x1, acc[1][1]);
            acc[1][2] = fma2(w1, x2, acc[1][2]);
            acc[2][0] = fma2(w2, x0, acc[2][0]);
            acc[2][1] = fma2(w2, x1, acc[2][1]);
            acc[2][2] = fma2(w2, x2, acc[2][2]);
            acc[3][0] = fma2(w3, x0, acc[3][0]);
            acc[3][1] = fma2(w3, x1, acc[3][1]);
            acc[3][2] = fma2(w3, x2, acc[3][2]);
        }
    }
}

__global__ __launch_bounds__(256, 1) void k_gru(
    float* __restrict__ h, const float* __restrict__ node_type,
    const float* __restrict__ Wih, const float* __restrict__ bhh,
    const float* __restrict__ Wattn, int level) {
    extern __shared__ __align__(16) float sm[];
    float* ws0 = sm + SM_WS0;
    float* ws1 = sm + SM_WS1;
    float* xs  = sm + SM_XS;
    float* hs  = sm + SM_HS;
    float* smnt = sm + SM_NT;                    // [3][384] W_ih node-type columns
    int*   snode = (int*)(sm + SM_META);
    float* sact  = sm + SM_META + TILE_N;
    float* srd   = sm + SM_META + 2 * TILE_N;
    int*   stype = (int*)(sm + SM_META + 3 * TILE_N);

    int t = threadIdx.x;
    int start = g_node_off[level], end = g_node_off[level + 1];
    int cnt = end - start;
    int ntiles = (cnt + TILE_N - 1) / TILE_N;
    int lane = t & 31;
    int i0 = lane << 2;
    int warp = t >> 5;
    int nb0 = warp * 6;

    // stage node-type weight columns once per block
    for (int idx = t; idx < 1152; idx += 256) {
        int c = idx % 3, r = idx / 3;
        smnt[c * 384 + r] = Wih[r * 131 + 128 + c];
    }

    for (int tile = blockIdx.x; tile < ntiles; tile += gridDim.x) {
        __syncthreads();                      // smnt ready (1st iter) / prior tile done
        if (t < TILE_N) {
            int slot = start + tile * TILE_N + t;
            int node = 0; float act = 0.f, rd = 0.f; int ty = 0;
            if (slot < end) {
                node = g_node_list[slot];
                float d = g_denom[node];
                if (d > 0.f) { act = 1.f; rd = 1.f / (d + 1e-16f); }
                float n1 = node_type[(size_t)node * 3 + 1];
                float n2 = node_type[(size_t)node * 3 + 2];
                ty = n1 > 0.5f ? 1 : (n2 > 0.5f ? 2 : 0);
            }
            snode[t] = node; sact[t] = act; srd[t] = rd; stype[t] = ty;
        }
        __syncthreads();
        // stage agg*rd -> xs and h -> hs, feature-major [feat][node]
        for (int idx = t; idx < TILE_N * 32; idx += 256) {
            int n = idx % TILE_N, j4 = idx / TILE_N;
            int node = snode[n];
            float rd = srd[n];
            float4 av = *(const float4*)&g_agg[(size_t)node * H + (j4 << 2)];
            float4 hv = *(const float4*)&h[(size_t)node * H + (j4 << 2)];
            int jb = j4 << 2;
            xs[(jb + 0) * XS3 + n] = av.x * rd;
            xs[(jb + 1) * XS3 + n] = av.y * rd;
            xs[(jb + 2) * XS3 + n] = av.z * rd;
            xs[(jb + 3) * XS3 + n] = av.w * rd;
            hs[(jb + 0) * XS3 + n] = hv.x;
            hs[(jb + 1) * XS3 + n] = hv.y;
            hs[(jb + 2) * XS3 + n] = hv.z;
            hs[(jb + 3) * XS3 + n] = hv.w;
        }
        // (gemm48 entry sync covers staging visibility)

        ull rr[4][3], zz[4][3];
        for (int chunk = 0; chunk < 3; chunk++) {
            ull ai[4][3], ah[4][3];
#pragma unroll
            for (int di = 0; di < 4; di++) {
                int row = chunk * H + i0 + di;
                float bb = g_bbig[row];
                float c0 = smnt[row], c1 = smnt[384 + row], c2 = smnt[768 + row];
                float b2 = bhh[row];
                ull bh2 = pack2(b2, b2);
#pragma unroll
                for (int p = 0; p < 3; p++) {
                    int n0 = nb0 + 2 * p;
                    int t0 = stype[n0], t1 = stype[n0 + 1];
                    float v0 = bb + (t0 == 1 ? c1 : (t0 == 2 ? c2 : c0));
                    float v1 = bb + (t1 == 1 ? c1 : (t1 == 2 ? c2 : c0));
                    ai[di][p] = pack2(v0, v1);
                    ah[di][p] = bh2;
                }
            }
            gemm48(ai, g_WbigT, chunk * H, xs, ws0, ws1, i0, nb0, t);
            gemm48(ah, g_WhhT, chunk * H, hs, ws0, ws1, i0, nb0, t);
            if (chunk == 0) {
#pragma unroll
                for (int di = 0; di < 4; di++)
#pragma unroll
                    for (int p = 0; p < 3; p++)
                        rr[di][p] = sig2(add2(ai[di][p], ah[di][p]));
            } else if (chunk == 1) {
#pragma unroll
                for (int di = 0; di < 4; di++)
#pragma unroll
                    for (int p = 0; p < 3; p++)
                        zz[di][p] = sig2(add2(ai[di][p], ah[di][p]));
            } else {
                float4 a1 = *(const float4*)&Wattn[i0];
                float4 a2 = *(const float4*)&Wattn[H + i0];
#pragma unroll
                for (int p = 0; p < 3; p++) {
                    float v[2][4];
#pragma unroll
                    for (int di = 0; di < 4; di++) {
                        float in0, in1, hn0, hn1, r0, r1, z0, z1, h0, h1;
                        unpack2(ai[di][p], in0, in1);
                        unpack2(ah[di][p], hn0, hn1);
                        unpack2(rr[di][p], r0, r1);
                        unpack2(zz[di][p], z0, z1);
                        ull hold = *(const ull*)&hs[(i0 + di) * XS3 + nb0 + (p << 1)];
                        unpack2(hold, h0, h1);
                        float n0 = tanh_(in0 + r0 * hn0);
                        float n1 = tanh_(in1 + r1 * hn1);
                        v[0][di] = (1.f - z0) * n0 + z0 * h0;
                        v[1][di] = (1.f - z1) * n1 + z1 * h1;
                    }
#pragma unroll
                    for (int half = 0; half < 2; half++) {
                        int nn = nb0 + (p << 1) + half;
                        int node = snode[nn];
                        bool act = sact[nn] > 0.f;
                        if (act) {
                            *(float4*)&h[(size_t)node * H + i0] =
                                make_float4(v[half][0], v[half][1], v[half][2], v[half][3]);
                        }
                        float s1 = v[half][0] * a1.x + v[half][1] * a1.y +
                                   v[half][2] * a1.z + v[half][3] * a1.w;
                        float s2 = v[half][0] * a2.x + v[half][1] * a2.y +
                                   v[half][2] * a2.z + v[half][3] * a2.w;
#pragma unroll
                        for (int off = 16; off; off >>= 1) {
                            s1 += __shfl_xor_sync(0xffffffffu, s1, off);
                            s2 += __shfl_xor_sync(0xffffffffu, s2, off);
                        }
                        if (lane == 0 && act) { g_p1[node] = s1; g_p2[node] = s2; }
                    }
                }
            }
        }
    }
}

// ---------------- launch ----------------
extern "C" void kernel_launch(void* const* d_in, const int* in_sizes, int n_in,
                              void* d_out, int out_size) {
    const float* node_embedding = (const float*)d_in[0];
    const float* node_type      = (const float*)d_in[1];
    const float* W_attn         = (const float*)d_in[2];
    const float* b_attn         = (const float*)d_in[3];
    const float* W_msg          = (const float*)d_in[4];
    const float* b_msg          = (const float*)d_in[5];
    const float* W_ih           = (const float*)d_in[6];
    const float* W_hh           = (const float*)d_in[7];
    const float* b_ih           = (const float*)d_in[8];
    const float* b_hh           = (const float*)d_in[9];
    const int*   edge_src       = (const int*)d_in[10];
    const int*   edge_dst       = (const int*)d_in[11];
    const int*   fnl            = (const int*)d_in[12];
    float* h = (float*)d_out;

    cudaFuncSetAttribute(k_gru, cudaFuncAttributeMaxDynamicSharedMemorySize, SM_BYTES);

    k_reset<<<4096, 256>>>();
    k_fuse<<<384, 128>>>(W_ih, W_msg, b_ih, b_msg);
    k_transpose<<<192, 256>>>(W_hh);
    k_count<<<1758, 256>>>(fnl, edge_dst);
    k_scan<<<1, 32>>>();
    k_scatter<<<1758, 256>>>(fnl, edge_src, edge_dst);
    k_init<<<6250, 256>>>(node_embedding, W_attn, h);

    for (int k = 1; k < DEPTH; k++) {
        k_edge<<<1024, 256>>>(h, b_attn, k);
        k_gru<<<148, 256, SM_BYTES>>>(h, node_type, W_ih, b_hh, W_attn, k);
    }
}